// round 8
// baseline (speedup 1.0000x reference)
#include <cuda_runtime.h>
#include <cstdint>

#define NQ 65536
#define NC 2048
#define AS 132   // activation smem row stride (floats)
#define WS 144   // weight-tile smem row stride (floats)

typedef unsigned long long ull;

// ------- device scratch (static __device__ globals: allocation-free) -------
__device__ float g_X[NQ * 128];    // [query_codes 64 | xyz_emb 63 | 0]
__device__ float g_DIR[NQ * 32];   // [dir_emb 27 | 0 x5]
__device__ float g_U[NQ * 128];    // X @ W2x   (skip-path partial)
__device__ float g_V[NQ * 64];     // dir @ Wd_dir + bd
__device__ int   g_hist[4096];
__device__ int   g_offs[4096];
__device__ int   g_perm[NQ];
__device__ float g_W0p[128 * 128];
__device__ float g_W2xp[128 * 128];
__device__ float g_W2hp[128 * 128];
__device__ float g_Wdfp[128 * 64];

// ------------------------- f32x2 helpers -----------------------------------
__device__ __forceinline__ ull pk2(float lo, float hi) {
    ull r; asm("mov.b64 %0,{%1,%2};" : "=l"(r) : "f"(lo), "f"(hi)); return r;
}
__device__ __forceinline__ void fma2(ull& c, ull a, ull b) {
    asm("fma.rn.f32x2 %0,%1,%2,%0;" : "+l"(c) : "l"(a), "l"(b));
}
__device__ __forceinline__ float2 up2(ull v) {
    float2 r; asm("mov.b64 {%0,%1},%2;" : "=f"(r.x), "=f"(r.y) : "l"(v)); return r;
}
__device__ __forceinline__ int wsw(int col) {
    int g = col >> 3;
    return g * 8 + (g >> 2) * 4 + (col & 7);
}
__device__ __forceinline__ int cell_of(float x, float y, float z) {
    int ix = min(15, max(0, (int)(x * 16.f)));
    int iy = min(15, max(0, (int)(y * 16.f)));
    int iz = min(15, max(0, (int)(z * 16.f)));
    return (ix << 8) | (iy << 4) | iz;
}

// --------------------- spatial counting sort of queries --------------------
__global__ void zero_hist() { g_hist[blockIdx.x * 256 + threadIdx.x] = 0; }

__global__ void hist_k(const float* __restrict__ qp) {
    int q = blockIdx.x * 256 + threadIdx.x;
    atomicAdd(&g_hist[cell_of(qp[3 * q], qp[3 * q + 1], qp[3 * q + 2])], 1);
}

__global__ void __launch_bounds__(1024) scan_k() {   // 1 block
    __shared__ int s[1024];
    int tid = threadIdx.x;
    int v[4]; int sum = 0;
#pragma unroll
    for (int i = 0; i < 4; i++) { v[i] = g_hist[tid * 4 + i]; sum += v[i]; }
    s[tid] = sum; __syncthreads();
    for (int off = 1; off < 1024; off <<= 1) {
        int t = (tid >= off) ? s[tid - off] : 0;
        __syncthreads();
        s[tid] += t;
        __syncthreads();
    }
    int run = tid ? s[tid - 1] : 0;
#pragma unroll
    for (int i = 0; i < 4; i++) { g_offs[tid * 4 + i] = run; run += v[i]; }
}

__global__ void scatter_k(const float* __restrict__ qp) {
    int q = blockIdx.x * 256 + threadIdx.x;
    int cell = cell_of(qp[3 * q], qp[3 * q + 1], qp[3 * q + 2]);
    int pos = atomicAdd(&g_offs[cell], 1);
    g_perm[pos] = q;
}

// ------------------------- weight prep -------------------------------------
__global__ void prep_weights(const float* __restrict__ W0,
                             const float* __restrict__ W2,
                             const float* __restrict__ Wd) {
    const int T0 = 16384, T1 = 16384, T2 = 16384, T3 = 8192;
    int total = T0 + T1 + T2 + T3;
    for (int i = blockIdx.x * blockDim.x + threadIdx.x; i < total;
         i += gridDim.x * blockDim.x) {
        if (i < T0) {
            int r = i >> 7, c = i & 127;
            g_W0p[i] = (r < 127) ? W0[r * 128 + c] : 0.f;
        } else if (i < T0 + T1) {
            int j = i - T0; int r = j >> 7, c = j & 127;
            g_W2xp[j] = (r < 127) ? W2[r * 128 + c] : 0.f;
        } else if (i < T0 + T1 + T2) {
            int j = i - T0 - T1; int r = j >> 7, c = j & 127;
            g_W2hp[j] = W2[(127 + r) * 128 + c];
        } else {
            int j = i - T0 - T1 - T2;
            g_Wdfp[j] = Wd[j];
        }
    }
}

// --------------------- pack xyz / dir embeddings ---------------------------
__global__ void pack_inputs(const float* __restrict__ xyzdir) {
    const int TA = NQ * 64;
    const int total = NQ * 64 + NQ * 32;
    for (int i = blockIdx.x * blockDim.x + threadIdx.x; i < total;
         i += gridDim.x * blockDim.x) {
        if (i < TA) {
            int q = i >> 6, e = i & 63;
            g_X[q * 128 + 64 + e] = (e < 63) ? xyzdir[q * 90 + e] : 0.f;
        } else {
            int j = i - TA; int q = j >> 5, e = j & 31;
            g_DIR[j] = (e < 27) ? xyzdir[q * 90 + 63 + e] : 0.f;
        }
    }
}

// ---------------- V = dir @ Wd[128:155] + bd  ------------------------------
__global__ void __launch_bounds__(256) vcomp(const float* __restrict__ Wd,
                                             const float* __restrict__ bd) {
    __shared__ float sw[27 * 64];
    __shared__ float sb[64];
    int tid = threadIdx.x;
    for (int i = tid; i < 27 * 64; i += 256) sw[i] = Wd[128 * 64 + i];
    if (tid < 64) sb[tid] = bd[tid];
    __syncthreads();
    int idx = blockIdx.x * 256 + tid;
    int q = idx >> 4, c0 = (idx & 15) * 4;
    float a0 = sb[c0], a1 = sb[c0 + 1], a2 = sb[c0 + 2], a3 = sb[c0 + 3];
#pragma unroll
    for (int k = 0; k < 27; k++) {
        float dv = g_DIR[q * 32 + k];
        a0 = fmaf(dv, sw[k * 64 + c0 + 0], a0);
        a1 = fmaf(dv, sw[k * 64 + c0 + 1], a1);
        a2 = fmaf(dv, sw[k * 64 + c0 + 2], a2);
        a3 = fmaf(dv, sw[k * 64 + c0 + 3], a3);
    }
    *reinterpret_cast<float4*>(g_V + (size_t)q * 64 + c0) = make_float4(a0, a1, a2, a3);
}

// ---- KNN(16): split-scan (2 threads/query) + merge + interpolation --------
// Thread pair (2s, 2s+1) handles query slot s: each scans half of the 2048
// candidates into a sorted top-16, then the pair merges via the bitonic
// partition lemma (set of 16 smallest preserved exactly). Odd half of the
// position array is staged with a +4 float4 pad so even/odd broadcast groups
// hit disjoint smem bank quads.
__global__ void __launch_bounds__(256) knn_interp(const int* __restrict__ indices,
                                                  const float* __restrict__ qp,
                                                  const float* __restrict__ cpos,
                                                  const float* __restrict__ codes) {
    __shared__ float4 sp[NC + 4];  // {x, y, z, ||c||^2}; [1024..) shifted by +4
    __shared__ float s_w[128 * 16];
    __shared__ int   s_i[128 * 16];
    __shared__ int   s_q[128];
    int tid = threadIdx.x;
    int ib = indices[0];
    const float* cp = cpos + (size_t)ib * NC * 3;
    const float* cc = codes + (size_t)ib * NC * 64;
    for (int c = tid; c < NC; c += 256) {
        float x = cp[c * 3 + 0], y = cp[c * 3 + 1], z = cp[c * 3 + 2];
        sp[c + ((c >= 1024) ? 4 : 0)] =
            make_float4(x, y, z, fmaf(x, x, fmaf(y, y, z * z)));
    }
    __syncthreads();

    int slot = tid >> 1;
    int half = tid & 1;
    int q = g_perm[blockIdx.x * 128 + slot];
    float qx = qp[q * 3 + 0], qy = qp[q * 3 + 1], qz = qp[q * 3 + 2];
    float qx2 = -2.f * qx, qy2 = -2.f * qy, qz2 = -2.f * qz;
    float q2 = fmaf(qx, qx, fmaf(qy, qy, qz * qz));

    unsigned bk[16];
#pragma unroll
    for (int j = 0; j < 16; j++) bk[j] = 0x7F7FFFFFu;
    float bnd = __uint_as_float(0x7F7FF800u) - q2;   // d2' threshold

    const float4* spp = sp + (half ? 1028 : 0);
    unsigned cbase = half ? 1024u : 0u;

    for (int c = 0; c < 1024; c += 4) {
#pragma unroll
        for (int i = 0; i < 4; i++) {
            float4 v = spp[c + i];
            float dp = fmaf(v.x, qx2, fmaf(v.y, qy2, fmaf(v.z, qz2, v.w)));
            if (dp < bnd) {
                float dfull = fmaxf(dp + q2, 0.f);   // clamp: keep bits ordered
                unsigned cur = (__float_as_uint(dfull) & 0xFFFFF800u)
                             | (cbase + (unsigned)(c + i));
#pragma unroll
                for (int j = 0; j < 16; j++) {
                    unsigned mn = min(bk[j], cur);
                    unsigned mx = max(bk[j], cur);
                    bk[j] = mn; cur = mx;
                }
                bnd = __uint_as_float(bk[15] & 0xFFFFF800u) - q2;
            }
        }
    }

    // pair-merge: min(A[i], B[15-i]) = set of 16 smallest of the union
    unsigned ot[16];
#pragma unroll
    for (int j = 0; j < 16; j++) ot[j] = __shfl_xor_sync(0xFFFFFFFFu, bk[j], 1);
#pragma unroll
    for (int j = 0; j < 16; j++) bk[j] = min(bk[j], ot[15 - j]);

    if (half == 0) {
        // exact distances -> normalized 1/d2 weights
        float w[16]; int ci[16]; float wsum = 0.f;
#pragma unroll
        for (int k = 0; k < 16; k++) {
            int c = (int)(bk[k] & 0x7FFu); ci[k] = c;
            float4 v = sp[(c >= 1024) ? (c + 4) : c];
            float dx = qx - v.x, dy = qy - v.y, dz = qz - v.z;
            float d2 = fmaf(dx, dx, fmaf(dy, dy, dz * dz)) + 1e-16f;
            w[k] = 1.0f / d2; wsum += w[k];
        }
        float inv = 1.0f / wsum;
#pragma unroll
        for (int k = 0; k < 16; k++) {
            s_w[slot * 16 + k] = w[k] * inv;
            s_i[slot * 16 + k] = ci[k];
        }
        s_q[slot] = q;
    }
    __syncwarp();   // pair and gather slots live in the same warp

    // warp-cooperative gather: warp w covers slots [w*16, w*16+16)
    int lane = tid & 31;
    int wslot = (tid >> 5) * 16;
    for (int s = 0; s < 16; s++) {
        int sl = wslot + s;
        int qq = s_q[sl];
        float a0 = 0.f, a1 = 0.f;
#pragma unroll
        for (int k = 0; k < 16; k++) {
            int cix = s_i[sl * 16 + k];
            float wk = s_w[sl * 16 + k];
            const float* row = cc + cix * 64;
            a0 = fmaf(wk, row[lane], a0);
            a1 = fmaf(wk, row[lane + 32], a1);
        }
        g_X[(size_t)qq * 128 + lane] = a0;
        g_X[(size_t)qq * 128 + 32 + lane] = a1;
    }
}

// ===================== fused MLP (entire network) ==========================
#define SMEM_FLOATS (128 * AS + 2 * 32 * WS + 128 + 192)

__global__ void __launch_bounds__(256, 2) fused_mlp(
    const float* __restrict__ W1, const float* __restrict__ W3,
    const float* __restrict__ Wf,
    const float* __restrict__ b0, const float* __restrict__ b1,
    const float* __restrict__ b2, const float* __restrict__ b3,
    const float* __restrict__ bf,
    const float* __restrict__ Wsig, const float* __restrict__ bs,
    const float* __restrict__ Wr,   const float* __restrict__ br,
    float* __restrict__ out)
{
    extern __shared__ float sm[];
    float* A   = sm;
    float* Wb  = sm + 128 * AS;
    float* wsv = Wb + 2 * 32 * WS;
    float* wrv = wsv + 128;

    int tid = threadIdx.x;
    int tx = tid & 15, ty = tid >> 4;
    int rowBlk = blockIdx.x * 128;
    const int wbase = tx * 8 + (tx >> 2) * 4;

    if (tid < 128) wsv[tid] = Wsig[tid];
    if (tid < 192) wrv[tid] = Wr[tid];

    {
        const float4* src = reinterpret_cast<const float4*>(g_X + (size_t)rowBlk * 128);
#pragma unroll
        for (int i = 0; i < 16; i++) {
            int f4 = tid + i * 256;
            float4 v = src[f4];
            int row = f4 >> 5, c4 = f4 & 31;
            *reinterpret_cast<float4*>(A + row * AS + c4 * 4) = v;
        }
    }

    const float* Wgs[6] = { g_W2xp, g_W0p, W1, g_W2hp, W3, Wf };
    const float* bgs[6] = { b0, b0, b1, b2, b3, bf };

    float sigR = 0.f;
    ull acc[8][4];

    for (int L = 0; L < 6; ++L) {
        const float* Wg = Wgs[L];
#pragma unroll
        for (int i = 0; i < 8; i++)
#pragma unroll
            for (int j = 0; j < 4; j++) acc[i][j] = 0ULL;

#pragma unroll
        for (int i = 0; i < 4; i++) {
            float4 v = reinterpret_cast<const float4*>(Wg)[tid * 4 + i];
            int flat = tid * 16 + i * 4;
            int k = flat >> 7, col = flat & 127;
            *reinterpret_cast<float4*>(Wb + k * WS + wsw(col)) = v;
        }
        __syncthreads();

        for (int t = 0; t < 4; t++) {
            float4 pf[4];
            if (t < 3) {
                const float4* g = reinterpret_cast<const float4*>(Wg + (t + 1) * 4096);
#pragma unroll
                for (int i = 0; i < 4; i++) pf[i] = g[tid * 4 + i];
            }
            const float* Wt = Wb + (t & 1) * (32 * WS);
#pragma unroll
            for (int k4 = 0; k4 < 8; k4++) {
                ulonglong2 wq0[4], wq1[4];
#pragma unroll
                for (int kk = 0; kk < 4; kk++) {
                    const float* wp = Wt + (k4 * 4 + kk) * WS + wbase;
                    wq0[kk] = *reinterpret_cast<const ulonglong2*>(wp);
                    wq1[kk] = *reinterpret_cast<const ulonglong2*>(wp + 4);
                }
#pragma unroll
                for (int r4 = 0; r4 < 2; r4++) {
                    float4 ar[4];
#pragma unroll
                    for (int r = 0; r < 4; r++)
                        ar[r] = *reinterpret_cast<const float4*>(
                            A + (ty * 8 + r4 * 4 + r) * AS + t * 32 + k4 * 4);
#pragma unroll
                    for (int kk = 0; kk < 4; kk++) {
#pragma unroll
                        for (int r = 0; r < 4; r++) {
                            float av = (kk == 0) ? ar[r].x : (kk == 1) ? ar[r].y
                                     : (kk == 2) ? ar[r].z : ar[r].w;
                            ull ad = pk2(av, av);
                            int ri = r4 * 4 + r;
                            fma2(acc[ri][0], ad, wq0[kk].x);
                            fma2(acc[ri][1], ad, wq0[kk].y);
                            fma2(acc[ri][2], ad, wq1[kk].x);
                            fma2(acc[ri][3], ad, wq1[kk].y);
                        }
                    }
                }
            }
            if (t < 3) {
                float* d = Wb + ((t + 1) & 1) * (32 * WS);
#pragma unroll
                for (int i = 0; i < 4; i++) {
                    int flat = tid * 16 + i * 4;
                    int k = flat >> 7, col = flat & 127;
                    *reinterpret_cast<float4*>(d + k * WS + wsw(col)) = pf[i];
                }
            }
            __syncthreads();
        }

        if (L == 0) {
#pragma unroll
            for (int i = 0; i < 8; i++) {
                size_t row = (size_t)(rowBlk + ty * 8 + i);
                float o[8];
#pragma unroll
                for (int j = 0; j < 4; j++) {
                    float2 v = up2(acc[i][j]); o[2 * j] = v.x; o[2 * j + 1] = v.y;
                }
                *reinterpret_cast<float4*>(g_U + row * 128 + tx * 8) =
                    make_float4(o[0], o[1], o[2], o[3]);
                *reinterpret_cast<float4*>(g_U + row * 128 + tx * 8 + 4) =
                    make_float4(o[4], o[5], o[6], o[7]);
            }
        } else {
            const float* bg = bgs[L];
            float4 bA = *reinterpret_cast<const float4*>(bg + tx * 8);
            float4 bB = *reinterpret_cast<const float4*>(bg + tx * 8 + 4);
            bool relu = (L != 5);
#pragma unroll
            for (int i = 0; i < 8; i++) {
                int row = ty * 8 + i;
                float o[8];
#pragma unroll
                for (int j = 0; j < 4; j++) {
                    float2 v = up2(acc[i][j]); o[2 * j] = v.x; o[2 * j + 1] = v.y;
                }
                if (L == 3) {
                    size_t gr = (size_t)(rowBlk + row);
                    float4 u0 = *reinterpret_cast<const float4*>(g_U + gr * 128 + tx * 8);
                    float4 u1 = *reinterpret_cast<const float4*>(g_U + gr * 128 + tx * 8 + 4);
                    o[0] += u0.x; o[1] += u0.y; o[2] += u0.z; o[3] += u0.w;
                    o[4] += u1.x; o[5] += u1.y; o[6] += u1.z; o[7] += u1.w;
                }
                o[0] += bA.x; o[1] += bA.y; o[2] += bA.z; o[3] += bA.w;
                o[4] += bB.x; o[5] += bB.y; o[6] += bB.z; o[7] += bB.w;
                if (relu) {
#pragma unroll
                    for (int c = 0; c < 8; c++) o[c] = fmaxf(o[c], 0.f);
                }
                *reinterpret_cast<float4*>(A + row * AS + tx * 8) =
                    make_float4(o[0], o[1], o[2], o[3]);
                *reinterpret_cast<float4*>(A + row * AS + tx * 8 + 4) =
                    make_float4(o[4], o[5], o[6], o[7]);
            }
        }
        __syncthreads();

        if (L == 4 && tid < 128) {
            float s = 0.f;
#pragma unroll
            for (int k4 = 0; k4 < 32; k4++) {
                float4 hv = *reinterpret_cast<const float4*>(A + tid * AS + k4 * 4);
                s = fmaf(hv.x, wsv[k4 * 4 + 0], s);
                s = fmaf(hv.y, wsv[k4 * 4 + 1], s);
                s = fmaf(hv.z, wsv[k4 * 4 + 2], s);
                s = fmaf(hv.w, wsv[k4 * 4 + 3], s);
            }
            sigR = s + bs[0];
        }
    }

    // ---- dir layer ----
    int tx8 = tid & 7, ty32 = tid >> 3;
    const int wb64 = tx8 * 8 + (tx8 >> 2) * 4;
    ull acc2[4][4];
#pragma unroll
    for (int i = 0; i < 4; i++)
#pragma unroll
        for (int j = 0; j < 4; j++) acc2[i][j] = 0ULL;

#pragma unroll
    for (int i = 0; i < 2; i++) {
        float4 v = reinterpret_cast<const float4*>(g_Wdfp)[tid * 2 + i];
        int flat = tid * 8 + i * 4;
        int k = flat >> 6, col = flat & 63;
        *reinterpret_cast<float4*>(Wb + k * WS + wsw(col)) = v;
    }
    __syncthreads();

    for (int t = 0; t < 4; t++) {
        float4 pf[2];
        if (t < 3) {
            const float4* g = reinterpret_cast<const float4*>(g_Wdfp + (t + 1) * 2048);
#pragma unroll
            for (int i = 0; i < 2; i++) pf[i] = g[tid * 2 + i];
        }
        const float* Wt = Wb + (t & 1) * (32 * WS);
#pragma unroll
        for (int k4 = 0; k4 < 8; k4++) {
            ulonglong2 wq0[4], wq1[4];
#pragma unroll
            for (int kk = 0; kk < 4; kk++) {
                const float* wp = Wt + (k4 * 4 + kk) * WS + wb64;
                wq0[kk] = *reinterpret_cast<const ulonglong2*>(wp);
                wq1[kk] = *reinterpret_cast<const ulonglong2*>(wp + 4);
            }
            float4 ar[4];
#pragma unroll
            for (int r = 0; r < 4; r++)
                ar[r] = *reinterpret_cast<const float4*>(
                    A + (ty32 * 4 + r) * AS + t * 32 + k4 * 4);
#pragma unroll
            for (int kk = 0; kk < 4; kk++) {
#pragma unroll
                for (int r = 0; r < 4; r++) {
                    float av = (kk == 0) ? ar[r].x : (kk == 1) ? ar[r].y
                             : (kk == 2) ? ar[r].z : ar[r].w;
                    ull ad = pk2(av, av);
                    fma2(acc2[r][0], ad, wq0[kk].x);
                    fma2(acc2[r][1], ad, wq0[kk].y);
                    fma2(acc2[r][2], ad, wq1[kk].x);
                    fma2(acc2[r][3], ad, wq1[kk].y);
                }
            }
        }
        if (t < 3) {
            float* d = Wb + ((t + 1) & 1) * (32 * WS);
#pragma unroll
            for (int i = 0; i < 2; i++) {
                int flat = tid * 8 + i * 4;
                int k = flat >> 6, col = flat & 63;
                *reinterpret_cast<float4*>(d + k * WS + wsw(col)) = pf[i];
            }
        }
        __syncthreads();
    }

#pragma unroll
    for (int r = 0; r < 4; r++) {
        int row = ty32 * 4 + r;
        size_t gr = (size_t)(rowBlk + row);
        float4 v0 = *reinterpret_cast<const float4*>(g_V + gr * 64 + tx8 * 8);
        float4 v1 = *reinterpret_cast<const float4*>(g_V + gr * 64 + tx8 * 8 + 4);
        float o[8];
#pragma unroll
        for (int j = 0; j < 4; j++) {
            float2 v = up2(acc2[r][j]); o[2 * j] = v.x; o[2 * j + 1] = v.y;
        }
        o[0] += v0.x; o[1] += v0.y; o[2] += v0.z; o[3] += v0.w;
        o[4] += v1.x; o[5] += v1.y; o[6] += v1.z; o[7] += v1.w;
#pragma unroll
        for (int c = 0; c < 8; c++) o[c] = fmaxf(o[c], 0.f);
        *reinterpret_cast<float4*>(A + row * AS + tx8 * 8) =
            make_float4(o[0], o[1], o[2], o[3]);
        *reinterpret_cast<float4*>(A + row * AS + tx8 * 8 + 4) =
            make_float4(o[4], o[5], o[6], o[7]);
    }
    __syncthreads();

    if (tid < 128) {
        float r0 = br[0], r1 = br[1], r2 = br[2];
#pragma unroll
        for (int k4 = 0; k4 < 16; k4++) {
            float4 dv = *reinterpret_cast<const float4*>(A + tid * AS + k4 * 4);
            const float* wr0 = wrv + k4 * 12;
            r0 = fmaf(dv.x, wr0[0], r0); r1 = fmaf(dv.x, wr0[1], r1); r2 = fmaf(dv.x, wr0[2], r2);
            r0 = fmaf(dv.y, wr0[3], r0); r1 = fmaf(dv.y, wr0[4], r1); r2 = fmaf(dv.y, wr0[5], r2);
            r0 = fmaf(dv.z, wr0[6], r0); r1 = fmaf(dv.z, wr0[7], r1); r2 = fmaf(dv.z, wr0[8], r2);
            r0 = fmaf(dv.w, wr0[9], r0); r1 = fmaf(dv.w, wr0[10], r1); r2 = fmaf(dv.w, wr0[11], r2);
        }
        *reinterpret_cast<float4*>(out + (size_t)(rowBlk + tid) * 4) =
            make_float4(r0, r1, r2, sigR);
    }
}

// ---------------------------------------------------------------------------
extern "C" void kernel_launch(void* const* d_in, const int* in_sizes, int n_in,
                              void* d_out, int out_size) {
    const int*   indices = (const int*)  d_in[0];
    const float* qp      = (const float*)d_in[1];
    const float* xyzdir  = (const float*)d_in[2];
    const float* cpos    = (const float*)d_in[3];
    const float* codes   = (const float*)d_in[4];
    const float* W0 = (const float*)d_in[5],  *b0 = (const float*)d_in[6];
    const float* W1 = (const float*)d_in[7],  *b1 = (const float*)d_in[8];
    const float* W2 = (const float*)d_in[9],  *b2 = (const float*)d_in[10];
    const float* W3 = (const float*)d_in[11], *b3 = (const float*)d_in[12];
    const float* Wf = (const float*)d_in[13], *bf = (const float*)d_in[14];
    const float* Wd = (const float*)d_in[15], *bd = (const float*)d_in[16];
    const float* Ws = (const float*)d_in[17], *bs = (const float*)d_in[18];
    const float* Wr = (const float*)d_in[19], *br = (const float*)d_in[20];
    float* out = (float*)d_out;

    const int smemBytes = SMEM_FLOATS * 4;
    cudaFuncSetAttribute(fused_mlp, cudaFuncAttributeMaxDynamicSharedMemorySize,
                         smemBytes);

    zero_hist<<<16, 256>>>();
    hist_k<<<NQ / 256, 256>>>(qp);
    scan_k<<<1, 1024>>>();
    scatter_k<<<NQ / 256, 256>>>(qp);
    prep_weights<<<224, 256>>>(W0, W2, Wd);
    pack_inputs<<<1024, 256>>>(xyzdir);
    vcomp<<<NQ * 16 / 256, 256>>>(Wd, bd);
    knn_interp<<<NQ / 128, 256>>>(indices, qp, cpos, codes);
    fused_mlp<<<NQ / 128, 256, smemBytes>>>(W1, W3, Wf, b0, b1, b2, b3, bf,
                                            Ws, bs, Wr, br, out);
}